// round 9
// baseline (speedup 1.0000x reference)
#include <cuda_runtime.h>
#include <stdint.h>

// Problem constants (fixed by setup_inputs)
#define BB 512        // batch rows
#define NN 100000     // reference points
#define DD 10         // logit dim
#define CC 3072       // x feature dim
#define KNN 50
#define RROWS 8       // rows per CTA tile in main pass
#define RGRP (BB / RROWS)   // 64
#define JCH 37        // j-chunks: 64*37 = 2368 CTAs = 8 exact waves @ occ 2 on 148 SMs
#define CAP 8192      // candidate buffer per row
#define TPB 256
#define TROWS 4       // rows per CTA in threshold kernel
#define TSAMP 2048    // sample size (first TSAMP points)
#define TMSEL 32      // threshold = TMSEL-th smallest sample key
#define TIECAP 512

// Scratch (static device globals — allocation-free)
// SoA layout: 3 float4 planes. A = x0..x3, B = x4..x7, C = (x8, x9, xsq, yf).
// Each warp-level LDG.128 over consecutive j touches exactly 4 cache lines
// (vs 12 with the old 48B AoS records) -> 3x fewer L1tex wavefronts.
__device__ float4             g_XA[NN];
__device__ float4             g_XB[NN];
__device__ float4             g_XC[NN];
__device__ float              g_L[BB * DD];
__device__ float              g_scale[BB];
__device__ float              g_T[BB];
__device__ int                g_ccount[BB];
__device__ unsigned long long g_cand[(size_t)BB * CAP]; // 32 MB

// Order-preserving float -> uint map and inverse
__device__ __forceinline__ unsigned mono(float f) {
    unsigned u = __float_as_uint(f);
    return u ^ ((unsigned)((int)u >> 31) | 0x80000000u);
}
__device__ __forceinline__ float unmono(unsigned v) {
    unsigned u = (v & 0x80000000u) ? (v ^ 0x80000000u) : ~v;
    return __uint_as_float(u);
}

// Key: xsq - 2*dot(L,x), fixed fmaf order — the SAME chain is used in every
// kernel (thresh, main, fallback), so keys are bitwise identical everywhere.
__device__ __forceinline__ float keyval(const float* L, const float* xv, float xsq) {
    float acc = 0.f;
#pragma unroll
    for (int c = 0; c < DD; c++) acc = fmaf(L[c], xv[c], acc);
    return fmaf(-2.f, acc, xsq);
}

// Parallel 256-bin select: find bin b s.t. prefix(b) < remaining <= prefix(b+1).
__device__ __forceinline__ void binselect256(unsigned* hist, unsigned* scanbuf,
                                             int remaining, unsigned* sel, unsigned* run) {
    int tid = threadIdx.x;
    unsigned cnt = (tid < 256) ? hist[tid] : 0u;
    scanbuf[tid] = cnt;
    __syncthreads();
#pragma unroll
    for (int off = 1; off < 256; off <<= 1) {
        unsigned v = (tid >= off && tid < 256) ? scanbuf[tid - off] : 0u;
        __syncthreads();
        if (tid < 256) scanbuf[tid] += v;
        __syncthreads();
    }
    if (tid < 256) {
        unsigned incl = scanbuf[tid];
        unsigned excl = incl - cnt;
        if (excl < (unsigned)remaining && incl >= (unsigned)remaining) {
            *sel = (unsigned)tid;
            *run = excl;
        }
    }
    __syncthreads();
}

// ---------------------------------------------------------------------------
// Kernel 0: zero counters + pack X rows into SoA float4 planes
// ---------------------------------------------------------------------------
__global__ void k_prep(const float* __restrict__ X, const int* __restrict__ Y) {
    int i = blockIdx.x * TPB + threadIdx.x;
    if (i < BB) g_ccount[i] = 0;
    if (i < NN) {
        float v[DD];
        float xsq = 0.f;
#pragma unroll
        for (int c = 0; c < DD; c++) { v[c] = X[i * DD + c]; xsq = fmaf(v[c], v[c], xsq); }
        g_XA[i] = make_float4(v[0], v[1], v[2], v[3]);
        g_XB[i] = make_float4(v[4], v[5], v[6], v[7]);
        g_XC[i] = make_float4(v[8], v[9], xsq, (float)(2 * Y[i] - 1));
    }
}

// ---------------------------------------------------------------------------
// Kernel 1: logits = x @ W + b (warp per row, 4 warps/CTA, 128 CTAs)
// ---------------------------------------------------------------------------
__global__ void k_logits(const float* __restrict__ x, const float* __restrict__ W,
                         const float* __restrict__ bias, float* __restrict__ out) {
    int warp = threadIdx.x >> 5, lane = threadIdx.x & 31;
    int row = blockIdx.x * 4 + warp;
    const float* xr = x + (size_t)row * CC;
    float acc[DD];
#pragma unroll
    for (int c = 0; c < DD; c++) acc[c] = 0.f;
    for (int k = lane; k < CC; k += 32) {
        float xv = xr[k];
        const float* wr = W + (size_t)k * DD;
#pragma unroll
        for (int c = 0; c < DD; c++) acc[c] = fmaf(xv, wr[c], acc[c]);
    }
#pragma unroll
    for (int c = 0; c < DD; c++)
#pragma unroll
        for (int off = 16; off > 0; off >>= 1)
            acc[c] += __shfl_down_sync(0xFFFFFFFFu, acc[c], off);
    if (lane == 0) {
        float mx = 0.f;
#pragma unroll
        for (int c = 0; c < DD; c++) {
            float l = acc[c] + bias[c];
            g_L[row * DD + c] = l;
            out[row * 11 + c] = l;
            mx = fmaxf(mx, fabsf(l));
        }
        g_scale[row] = 2.f * mx;
    }
}

// ---------------------------------------------------------------------------
// Kernel 2: fused sample + threshold — 4 rows/CTA, sample keys in smem,
//           per-row exact radix-select (parallel bin select) -> g_T[row]
// ---------------------------------------------------------------------------
__global__ void k_thresh2() {
    __shared__ unsigned skey[TROWS][TSAMP];   // 32 KB
    __shared__ unsigned hist[256];
    __shared__ unsigned scanbuf[TPB];
    __shared__ unsigned s_sel, s_run;
    int tid = threadIdx.x;
    int row0 = blockIdx.x * TROWS;
    float L[TROWS][DD];
#pragma unroll
    for (int r = 0; r < TROWS; r++)
#pragma unroll
        for (int c = 0; c < DD; c++) L[r][c] = g_L[(row0 + r) * DD + c];
    for (int s = tid; s < TSAMP; s += TPB) {
        float4 a = g_XA[s], b = g_XB[s], c4 = g_XC[s];
        float xv[DD] = {a.x, a.y, a.z, a.w, b.x, b.y, b.z, b.w, c4.x, c4.y};
#pragma unroll
        for (int r = 0; r < TROWS; r++) skey[r][s] = mono(keyval(L[r], xv, c4.z));
    }
    __syncthreads();
    for (int r = 0; r < TROWS; r++) {
        unsigned prefix = 0;
        int remaining = TMSEL;
        for (int pass = 0; pass < 4; pass++) {
            int shift = 24 - 8 * pass;
            unsigned maskhi = pass ? (0xFFFFFFFFu << (32 - 8 * pass)) : 0u;
            if (tid < 256) hist[tid] = 0u;
            __syncthreads();
            for (int i = tid; i < TSAMP; i += TPB) {
                unsigned u = skey[r][i];
                if ((u & maskhi) == prefix) atomicAdd(&hist[(u >> shift) & 255], 1u);
            }
            __syncthreads();
            binselect256(hist, scanbuf, remaining, &s_sel, &s_run);
            remaining -= (int)s_run;
            prefix |= s_sel << shift;
            __syncthreads();
        }
        if (tid == 0) g_T[row0 + r] = unmono(prefix);
        __syncthreads();
    }
}

// ---------------------------------------------------------------------------
// Kernel 3: main pass — scalar FFMA, 8 rows/CTA, 2 CTAs/SM,
//           SoA loads (4 lines per LDG.128), 2 points per iteration
// ---------------------------------------------------------------------------
__global__ void __launch_bounds__(TPB, 2) k_main() {
    int tid = threadIdx.x;
    int row0 = blockIdx.x * RROWS;
    float L[RROWS][DD];
    float Tf[RROWS];
#pragma unroll
    for (int r = 0; r < RROWS; r++) {
        Tf[r] = g_T[row0 + r];
#pragma unroll
        for (int c = 0; c < DD; c++) L[r][c] = g_L[(row0 + r) * DD + c];
    }

    const int chunk = (NN + JCH - 1) / JCH;
    int jbeg = blockIdx.y * chunk;
    int jend = min(NN, jbeg + chunk);

    for (int j = jbeg + tid; j < jend; j += 2 * TPB) {
        int j2 = j + TPB;
        int j2c = (j2 < jend) ? j2 : j;   // clamp (loads stay unpredicated)
        // front-batch all 6 coalesced loads
        float4 a0 = g_XA[j],   b0 = g_XB[j],   c0 = g_XC[j];
        float4 a1 = g_XA[j2c], b1 = g_XB[j2c], c1 = g_XC[j2c];

        float xv0[DD] = {a0.x, a0.y, a0.z, a0.w, b0.x, b0.y, b0.z, b0.w, c0.x, c0.y};
        float xv1[DD] = {a1.x, a1.y, a1.z, a1.w, b1.x, b1.y, b1.z, b1.w, c1.x, c1.y};
#pragma unroll
        for (int r = 0; r < RROWS; r++) {
            float k0 = keyval(L[r], xv0, c0.z);
            float k1 = keyval(L[r], xv1, c1.z);
            if (k0 <= Tf[r]) {
                int row = row0 + r;
                int slot = atomicAdd(&g_ccount[row], 1);
                if (slot < CAP)
                    g_cand[(size_t)row * CAP + slot] =
                        ((unsigned long long)mono(k0) << 32) | (unsigned)j;
            }
            if (j2 < jend && k1 <= Tf[r]) {
                int row = row0 + r;
                int slot = atomicAdd(&g_ccount[row], 1);
                if (slot < CAP)
                    g_cand[(size_t)row * CAP + slot] =
                        ((unsigned long long)mono(k1) << 32) | (unsigned)j2;
            }
        }
    }
}

// ---------------------------------------------------------------------------
// Kernel 4: correctness net — exact per-row bisection if candidates bad
//           (normally exits immediately; deterministic)
// ---------------------------------------------------------------------------
__global__ void k_fallback() {
    int row = blockIdx.x, tid = threadIdx.x;
    int c = g_ccount[row];
    if (c >= KNN && c <= CAP) return;
    float L[DD];
#pragma unroll
    for (int i = 0; i < DD; i++) L[i] = g_L[row * DD + i];
    __shared__ int scnt[TPB];
    unsigned lo = 0u, hi = 0xFFFFFFFFu;
    for (int it = 0; it < 32 && lo < hi; it++) {
        unsigned mid = lo + ((hi - lo) >> 1);
        int cnt = 0;
        for (int j = tid; j < NN; j += TPB) {
            float4 a = g_XA[j], b = g_XB[j], c4 = g_XC[j];
            float xv[DD] = {a.x, a.y, a.z, a.w, b.x, b.y, b.z, b.w, c4.x, c4.y};
            cnt += (mono(keyval(L, xv, c4.z)) <= mid);
        }
        scnt[tid] = cnt;
        __syncthreads();
        for (int st = TPB / 2; st > 0; st >>= 1) {
            if (tid < st) scnt[tid] += scnt[tid + st];
            __syncthreads();
        }
        int tot = scnt[0];
        __syncthreads();
        if (tot >= KNN) hi = mid; else lo = mid + 1;
    }
    if (tid == 0) g_ccount[row] = 0;
    __syncthreads();
    for (int j = tid; j < NN; j += TPB) {
        float4 a = g_XA[j], b = g_XB[j], c4 = g_XC[j];
        float xv[DD] = {a.x, a.y, a.z, a.w, b.x, b.y, b.z, b.w, c4.x, c4.y};
        unsigned u = mono(keyval(L, xv, c4.z));
        if (u <= lo) {
            int slot = atomicAdd(&g_ccount[row], 1);
            if (slot < CAP)
                g_cand[(size_t)row * CAP + slot] = ((unsigned long long)u << 32) | (unsigned)j;
        }
    }
}

// ---------------------------------------------------------------------------
// Kernel 5: per-row exact radix-select of 50th key among candidates
//           (parallel bin select), tie-break by smallest index, sum votes
// ---------------------------------------------------------------------------
__global__ void k_final(float* __restrict__ out) {
    int row = blockIdx.x, tid = threadIdx.x;
    int c = min(g_ccount[row], CAP);
    const unsigned long long* cd = &g_cand[(size_t)row * CAP];
    __shared__ unsigned hist[256];
    __shared__ unsigned scanbuf[TPB];
    __shared__ unsigned s_sel, s_run;
    unsigned prefix = 0;
    int remaining = KNN;
    for (int pass = 0; pass < 4; pass++) {
        int shift = 24 - 8 * pass;
        unsigned maskhi = pass ? (0xFFFFFFFFu << (32 - 8 * pass)) : 0u;
        if (tid < 256) hist[tid] = 0u;
        __syncthreads();
        for (int i = tid; i < c; i += TPB) {
            unsigned u = (unsigned)(cd[i] >> 32);
            if ((u & maskhi) == prefix) atomicAdd(&hist[(u >> shift) & 255], 1u);
        }
        __syncthreads();
        binselect256(hist, scanbuf, remaining, &s_sel, &s_run);
        remaining -= (int)s_run;
        prefix |= s_sel << shift;
        __syncthreads();
    }
    unsigned k50 = prefix;
    int t = remaining;  // take t smallest-index elements among key==k50 ties

    __shared__ int s_tn;
    __shared__ unsigned tiebuf[TIECAP];
    if (tid == 0) s_tn = 0;
    __syncthreads();
    float local = 0.f;
    for (int i = tid; i < c; i += TPB) {
        unsigned long long v = cd[i];
        unsigned u = (unsigned)(v >> 32);
        unsigned j = (unsigned)(v & 0xFFFFFFFFu);
        if (u < k50) {
            local += g_XC[j].w;  // yf
        } else if (u == k50) {
            int p = atomicAdd(&s_tn, 1);
            if (p < TIECAP) tiebuf[p] = j;
        }
    }
    __syncthreads();
    int nt = min(s_tn, TIECAP);
    for (int i = tid; i < nt; i += TPB) {
        unsigned ji = tiebuf[i];
        int rank = 0;
        for (int k = 0; k < nt; k++) rank += (tiebuf[k] < ji);
        if (rank < t) local += g_XC[ji].w;
    }
    __shared__ float sv[TPB];
    sv[tid] = local;
    __syncthreads();
    for (int st = TPB / 2; st > 0; st >>= 1) {
        if (tid < st) sv[tid] += sv[tid + st];
        __syncthreads();
    }
    if (tid == 0) {
        float v = sv[0];  // + BIAS (= 0)
        float sgn = (v > 0.f) ? 1.f : ((v < 0.f) ? -1.f : 0.f);
        out[row * 11 + 10] = sgn * g_scale[row];
    }
}

// ---------------------------------------------------------------------------
extern "C" void kernel_launch(void* const* d_in, const int* in_sizes, int n_in,
                              void* d_out, int out_size) {
    const float* x    = (const float*)d_in[0];
    const float* W    = (const float*)d_in[1];
    const float* bias = (const float*)d_in[2];
    const float* X    = (const float*)d_in[3];
    const int*   Y    = (const int*)d_in[4];
    float* out = (float*)d_out;

    k_prep<<<(NN + TPB - 1) / TPB, TPB>>>(X, Y);
    k_logits<<<BB / 4, 128>>>(x, W, bias, out);
    k_thresh2<<<BB / TROWS, TPB>>>();
    k_main<<<dim3(RGRP, JCH), TPB>>>();
    k_fallback<<<BB, TPB>>>();
    k_final<<<BB, TPB>>>(out);
}

// round 10
// speedup vs baseline: 1.7237x; 1.7237x over previous
#include <cuda_runtime.h>
#include <stdint.h>

// Problem constants (fixed by setup_inputs)
#define BB 512        // batch rows
#define NN 100000     // reference points
#define DD 10         // logit dim
#define CC 3072       // x feature dim
#define KNN 50
#define RROWS 4       // rows per CTA tile in main pass (low regs -> 4 CTAs/SM)
#define RGRP (BB / RROWS)   // 128
#define JCH 18        // j-chunks: 128*18 = 2304 CTAs
#define CAP 8192      // global candidate buffer per row
#define CCAP 256      // per-CTA smem candidate staging per row
#define TPB 256
#define TROWS 4       // rows per CTA in threshold kernel
#define TSAMP 2048    // sample size (first TSAMP points)
#define TMSEL 32      // threshold = TMSEL-th smallest sample key
#define TIECAP 512
#define PREP_BLOCKS ((NN + TPB - 1) / TPB)   // 391
#define LOGITS_BLOCKS (BB / 8)               // 64 (8 warps per block)

// Scratch (static device globals — allocation-free)
// SoA float4 planes: A = x0..x3, B = x4..x7, C = (x8, x9, xsq, yf).
__device__ float4             g_XA[NN];
__device__ float4             g_XB[NN];
__device__ float4             g_XC[NN];
__device__ float              g_L[BB * DD];
__device__ float              g_scale[BB];
__device__ float              g_T[BB];
__device__ int                g_ccount[BB];
__device__ unsigned long long g_cand[(size_t)BB * CAP]; // 32 MB

// Order-preserving float -> uint map and inverse
__device__ __forceinline__ unsigned mono(float f) {
    unsigned u = __float_as_uint(f);
    return u ^ ((unsigned)((int)u >> 31) | 0x80000000u);
}
__device__ __forceinline__ float unmono(unsigned v) {
    unsigned u = (v & 0x80000000u) ? (v ^ 0x80000000u) : ~v;
    return __uint_as_float(u);
}

// Key: xsq - 2*dot(L,x), fixed fmaf order — SAME chain in every kernel,
// so keys are bitwise identical everywhere.
__device__ __forceinline__ float keyval(const float* L, const float* xv, float xsq) {
    float acc = 0.f;
#pragma unroll
    for (int c = 0; c < DD; c++) acc = fmaf(L[c], xv[c], acc);
    return fmaf(-2.f, acc, xsq);
}

// Parallel 256-bin select: find bin b s.t. prefix(b) < remaining <= prefix(b+1).
__device__ __forceinline__ void binselect256(unsigned* hist, unsigned* scanbuf,
                                             int remaining, unsigned* sel, unsigned* run) {
    int tid = threadIdx.x;
    unsigned cnt = (tid < 256) ? hist[tid] : 0u;
    scanbuf[tid] = cnt;
    __syncthreads();
#pragma unroll
    for (int off = 1; off < 256; off <<= 1) {
        unsigned v = (tid >= off && tid < 256) ? scanbuf[tid - off] : 0u;
        __syncthreads();
        if (tid < 256) scanbuf[tid] += v;
        __syncthreads();
    }
    if (tid < 256) {
        unsigned incl = scanbuf[tid];
        unsigned excl = incl - cnt;
        if (excl < (unsigned)remaining && incl >= (unsigned)remaining) {
            *sel = (unsigned)tid;
            *run = excl;
        }
    }
    __syncthreads();
}

// ---------------------------------------------------------------------------
// Kernel 0 (fused): blocks [0,PREP_BLOCKS) pack X into SoA + zero counters;
//                   blocks [PREP_BLOCKS, +LOGITS_BLOCKS) compute logits.
// ---------------------------------------------------------------------------
__global__ void k_setup(const float* __restrict__ X, const int* __restrict__ Y,
                        const float* __restrict__ x, const float* __restrict__ W,
                        const float* __restrict__ bias, float* __restrict__ out) {
    int tid = threadIdx.x;
    if (blockIdx.x < PREP_BLOCKS) {
        int i = blockIdx.x * TPB + tid;
        if (i < BB) g_ccount[i] = 0;
        if (i < NN) {
            float v[DD];
            float xsq = 0.f;
#pragma unroll
            for (int c = 0; c < DD; c++) { v[c] = X[i * DD + c]; xsq = fmaf(v[c], v[c], xsq); }
            g_XA[i] = make_float4(v[0], v[1], v[2], v[3]);
            g_XB[i] = make_float4(v[4], v[5], v[6], v[7]);
            g_XC[i] = make_float4(v[8], v[9], xsq, (float)(2 * Y[i] - 1));
        }
    } else {
        int warp = tid >> 5, lane = tid & 31;
        int row = (blockIdx.x - PREP_BLOCKS) * 8 + warp;
        const float* xr = x + (size_t)row * CC;
        float acc[DD];
#pragma unroll
        for (int c = 0; c < DD; c++) acc[c] = 0.f;
        for (int k = lane; k < CC; k += 32) {
            float xv = xr[k];
            const float* wr = W + (size_t)k * DD;
#pragma unroll
            for (int c = 0; c < DD; c++) acc[c] = fmaf(xv, wr[c], acc[c]);
        }
#pragma unroll
        for (int c = 0; c < DD; c++)
#pragma unroll
            for (int off = 16; off > 0; off >>= 1)
                acc[c] += __shfl_down_sync(0xFFFFFFFFu, acc[c], off);
        if (lane == 0) {
            float mx = 0.f;
#pragma unroll
            for (int c = 0; c < DD; c++) {
                float l = acc[c] + bias[c];
                g_L[row * DD + c] = l;
                out[row * 11 + c] = l;
                mx = fmaxf(mx, fabsf(l));
            }
            g_scale[row] = 2.f * mx;
        }
    }
}

// ---------------------------------------------------------------------------
// Kernel 1: fused sample + threshold — 4 rows/CTA, sample keys in smem,
//           per-row exact radix-select (parallel bin select) -> g_T[row]
// ---------------------------------------------------------------------------
__global__ void k_thresh2() {
    __shared__ unsigned skey[TROWS][TSAMP];   // 32 KB
    __shared__ unsigned hist[256];
    __shared__ unsigned scanbuf[TPB];
    __shared__ unsigned s_sel, s_run;
    int tid = threadIdx.x;
    int row0 = blockIdx.x * TROWS;
    float L[TROWS][DD];
#pragma unroll
    for (int r = 0; r < TROWS; r++)
#pragma unroll
        for (int c = 0; c < DD; c++) L[r][c] = g_L[(row0 + r) * DD + c];
    for (int s = tid; s < TSAMP; s += TPB) {
        float4 a = g_XA[s], b = g_XB[s], c4 = g_XC[s];
        float xv[DD] = {a.x, a.y, a.z, a.w, b.x, b.y, b.z, b.w, c4.x, c4.y};
#pragma unroll
        for (int r = 0; r < TROWS; r++) skey[r][s] = mono(keyval(L[r], xv, c4.z));
    }
    __syncthreads();
    for (int r = 0; r < TROWS; r++) {
        unsigned prefix = 0;
        int remaining = TMSEL;
        for (int pass = 0; pass < 4; pass++) {
            int shift = 24 - 8 * pass;
            unsigned maskhi = pass ? (0xFFFFFFFFu << (32 - 8 * pass)) : 0u;
            if (tid < 256) hist[tid] = 0u;
            __syncthreads();
            for (int i = tid; i < TSAMP; i += TPB) {
                unsigned u = skey[r][i];
                if ((u & maskhi) == prefix) atomicAdd(&hist[(u >> shift) & 255], 1u);
            }
            __syncthreads();
            binselect256(hist, scanbuf, remaining, &s_sel, &s_run);
            remaining -= (int)s_run;
            prefix |= s_sel << shift;
            __syncthreads();
        }
        if (tid == 0) g_T[row0 + r] = unmono(prefix);
        __syncthreads();
    }
}

// ---------------------------------------------------------------------------
// Kernel 2: main pass — 4 rows/CTA, 4 CTAs/SM (32 warps), smem candidate
//           staging (smem atomics in hot loop, one global atomic per row/CTA)
// ---------------------------------------------------------------------------
__global__ void __launch_bounds__(TPB, 4) k_main() {
    __shared__ unsigned long long sbuf[RROWS][CCAP];   // 8 KB
    __shared__ int scnt[RROWS];
    __shared__ int sbase[RROWS];
    int tid = threadIdx.x;
    int row0 = blockIdx.x * RROWS;
    if (tid < RROWS) scnt[tid] = 0;
    float L[RROWS][DD];
    float Tf[RROWS];
#pragma unroll
    for (int r = 0; r < RROWS; r++) {
        Tf[r] = g_T[row0 + r];
#pragma unroll
        for (int c = 0; c < DD; c++) L[r][c] = g_L[(row0 + r) * DD + c];
    }
    __syncthreads();

    const int chunk = (NN + JCH - 1) / JCH;
    int jbeg = blockIdx.y * chunk;
    int jend = min(NN, jbeg + chunk);

    for (int j = jbeg + tid; j < jend; j += TPB) {
        float4 a = g_XA[j], b = g_XB[j], c4 = g_XC[j];
        float xv[DD] = {a.x, a.y, a.z, a.w, b.x, b.y, b.z, b.w, c4.x, c4.y};
#pragma unroll
        for (int r = 0; r < RROWS; r++) {
            float k = keyval(L[r], xv, c4.z);
            if (k <= Tf[r]) {
                int slot = atomicAdd(&scnt[r], 1);      // smem atomic: ~35 cyc
                if (slot < CCAP)
                    sbuf[r][slot] = ((unsigned long long)mono(k) << 32) | (unsigned)j;
            }
        }
    }
    __syncthreads();

    // Flush staged candidates: one global atomic per row, coalesced stores.
    if (tid < RROWS) {
        int r = tid;
        int n = scnt[r];
        // overflow (never expected): force ccount > CAP so fallback recomputes
        int add = (n > CCAP) ? (CAP + 1) : n;
        sbase[r] = atomicAdd(&g_ccount[row0 + r], add);
    }
    __syncthreads();
#pragma unroll
    for (int r = 0; r < RROWS; r++) {
        int n = min(scnt[r], CCAP);
        int base = sbase[r];
        for (int i = tid; i < n; i += TPB) {
            int slot = base + i;
            if (slot < CAP) g_cand[(size_t)(row0 + r) * CAP + slot] = sbuf[r][i];
        }
    }
}

// ---------------------------------------------------------------------------
// Kernel 3: correctness net — exact per-row bisection if candidates bad
//           (normally exits immediately; deterministic)
// ---------------------------------------------------------------------------
__global__ void k_fallback() {
    int row = blockIdx.x, tid = threadIdx.x;
    int c = g_ccount[row];
    if (c >= KNN && c <= CAP) return;
    float L[DD];
#pragma unroll
    for (int i = 0; i < DD; i++) L[i] = g_L[row * DD + i];
    __shared__ int scnt[TPB];
    unsigned lo = 0u, hi = 0xFFFFFFFFu;
    for (int it = 0; it < 32 && lo < hi; it++) {
        unsigned mid = lo + ((hi - lo) >> 1);
        int cnt = 0;
        for (int j = tid; j < NN; j += TPB) {
            float4 a = g_XA[j], b = g_XB[j], c4 = g_XC[j];
            float xv[DD] = {a.x, a.y, a.z, a.w, b.x, b.y, b.z, b.w, c4.x, c4.y};
            cnt += (mono(keyval(L, xv, c4.z)) <= mid);
        }
        scnt[tid] = cnt;
        __syncthreads();
        for (int st = TPB / 2; st > 0; st >>= 1) {
            if (tid < st) scnt[tid] += scnt[tid + st];
            __syncthreads();
        }
        int tot = scnt[0];
        __syncthreads();
        if (tot >= KNN) hi = mid; else lo = mid + 1;
    }
    if (tid == 0) g_ccount[row] = 0;
    __syncthreads();
    for (int j = tid; j < NN; j += TPB) {
        float4 a = g_XA[j], b = g_XB[j], c4 = g_XC[j];
        float xv[DD] = {a.x, a.y, a.z, a.w, b.x, b.y, b.z, b.w, c4.x, c4.y};
        unsigned u = mono(keyval(L, xv, c4.z));
        if (u <= lo) {
            int slot = atomicAdd(&g_ccount[row], 1);
            if (slot < CAP)
                g_cand[(size_t)row * CAP + slot] = ((unsigned long long)u << 32) | (unsigned)j;
        }
    }
}

// ---------------------------------------------------------------------------
// Kernel 4: per-row exact radix-select of 50th key among candidates
//           (parallel bin select), tie-break by smallest index, sum votes
// ---------------------------------------------------------------------------
__global__ void k_final(float* __restrict__ out) {
    int row = blockIdx.x, tid = threadIdx.x;
    int c = min(g_ccount[row], CAP);
    const unsigned long long* cd = &g_cand[(size_t)row * CAP];
    __shared__ unsigned hist[256];
    __shared__ unsigned scanbuf[TPB];
    __shared__ unsigned s_sel, s_run;
    unsigned prefix = 0;
    int remaining = KNN;
    for (int pass = 0; pass < 4; pass++) {
        int shift = 24 - 8 * pass;
        unsigned maskhi = pass ? (0xFFFFFFFFu << (32 - 8 * pass)) : 0u;
        if (tid < 256) hist[tid] = 0u;
        __syncthreads();
        for (int i = tid; i < c; i += TPB) {
            unsigned u = (unsigned)(cd[i] >> 32);
            if ((u & maskhi) == prefix) atomicAdd(&hist[(u >> shift) & 255], 1u);
        }
        __syncthreads();
        binselect256(hist, scanbuf, remaining, &s_sel, &s_run);
        remaining -= (int)s_run;
        prefix |= s_sel << shift;
        __syncthreads();
    }
    unsigned k50 = prefix;
    int t = remaining;  // take t smallest-index elements among key==k50 ties

    __shared__ int s_tn;
    __shared__ unsigned tiebuf[TIECAP];
    if (tid == 0) s_tn = 0;
    __syncthreads();
    float local = 0.f;
    for (int i = tid; i < c; i += TPB) {
        unsigned long long v = cd[i];
        unsigned u = (unsigned)(v >> 32);
        unsigned j = (unsigned)(v & 0xFFFFFFFFu);
        if (u < k50) {
            local += g_XC[j].w;  // yf
        } else if (u == k50) {
            int p = atomicAdd(&s_tn, 1);
            if (p < TIECAP) tiebuf[p] = j;
        }
    }
    __syncthreads();
    int nt = min(s_tn, TIECAP);
    for (int i = tid; i < nt; i += TPB) {
        unsigned ji = tiebuf[i];
        int rank = 0;
        for (int k = 0; k < nt; k++) rank += (tiebuf[k] < ji);
        if (rank < t) local += g_XC[ji].w;
    }
    __shared__ float sv[TPB];
    sv[tid] = local;
    __syncthreads();
    for (int st = TPB / 2; st > 0; st >>= 1) {
        if (tid < st) sv[tid] += sv[tid + st];
        __syncthreads();
    }
    if (tid == 0) {
        float v = sv[0];  // + BIAS (= 0)
        float sgn = (v > 0.f) ? 1.f : ((v < 0.f) ? -1.f : 0.f);
        out[row * 11 + 10] = sgn * g_scale[row];
    }
}

// ---------------------------------------------------------------------------
extern "C" void kernel_launch(void* const* d_in, const int* in_sizes, int n_in,
                              void* d_out, int out_size) {
    const float* x    = (const float*)d_in[0];
    const float* W    = (const float*)d_in[1];
    const float* bias = (const float*)d_in[2];
    const float* X    = (const float*)d_in[3];
    const int*   Y    = (const int*)d_in[4];
    float* out = (float*)d_out;

    k_setup<<<PREP_BLOCKS + LOGITS_BLOCKS, TPB>>>(X, Y, x, W, bias, out);
    k_thresh2<<<BB / TROWS, TPB>>>();
    k_main<<<dim3(RGRP, JCH), TPB>>>();
    k_fallback<<<BB, TPB>>>();
    k_final<<<BB, TPB>>>(out);
}